// round 1
// baseline (speedup 1.0000x reference)
#include <cuda_runtime.h>
#include <cstddef>

// Hin2vec layer: per-element gather-dot-sigmoid + CE loss.
// B=262144, N=1e6, R=64, H=128. DRAM-bound on random Wx gathers.

#define H_DIM 128
#define WARPS_PER_BLOCK 8

__global__ void hin_zero_loss(float* __restrict__ loss_ptr) {
    if (threadIdx.x == 0) *loss_ptr = 0.0f;
}

__global__ void __launch_bounds__(WARPS_PER_BLOCK * 32)
hin_main(const int* __restrict__ x,
         const int* __restrict__ y,
         const int* __restrict__ r,
         const int* __restrict__ l,
         const float4* __restrict__ Wx,   // [N, H/4]
         const float4* __restrict__ Wr,   // [R, H/4]
         float* __restrict__ out,         // [B, 2] logits
         float* __restrict__ loss_out,    // scalar (may be null)
         int B, float invB)
{
    const int wid  = threadIdx.x >> 5;
    const int lane = threadIdx.x & 31;
    const int i    = blockIdx.x * WARPS_PER_BLOCK + wid;

    __shared__ float sloss[WARPS_PER_BLOCK];

    float my_loss = 0.0f;

    if (i < B) {
        const int xi = __ldg(x + i);
        const int yi = __ldg(y + i);
        const int ri = __ldg(r + i);

        // One warp gathers one 512B row per table: lane -> float4.
        const float4 ax = __ldg(Wx + (size_t)xi * (H_DIM / 4) + lane);
        const float4 ay = __ldg(Wx + (size_t)yi * (H_DIM / 4) + lane);
        const float4 ar = __ldg(Wr + (size_t)ri * (H_DIM / 4) + lane);

        // regularization weight: s*(1-s) with s = sigmoid(clamp(embr, -6, 6))
        float acc;
        {
            float e0 = fminf(fmaxf(ar.x, -6.0f), 6.0f);
            float e1 = fminf(fmaxf(ar.y, -6.0f), 6.0f);
            float e2 = fminf(fmaxf(ar.z, -6.0f), 6.0f);
            float e3 = fminf(fmaxf(ar.w, -6.0f), 6.0f);
            float s0 = 1.0f / (1.0f + expf(-e0));
            float s1 = 1.0f / (1.0f + expf(-e1));
            float s2 = 1.0f / (1.0f + expf(-e2));
            float s3 = 1.0f / (1.0f + expf(-e3));
            acc  = ax.x * ay.x * (s0 * (1.0f - s0));
            acc += ax.y * ay.y * (s1 * (1.0f - s1));
            acc += ax.z * ay.z * (s2 * (1.0f - s2));
            acc += ax.w * ay.w * (s3 * (1.0f - s3));
        }

        // warp-wide dot reduce
        #pragma unroll
        for (int o = 16; o > 0; o >>= 1)
            acc += __shfl_xor_sync(0xFFFFFFFFu, acc, o);

        if (lane == 0) {
            const float p = 1.0f / (1.0f + expf(-acc));
            // logits = [p, 1-p]
            float2 lg;
            lg.x = p;
            lg.y = 1.0f - p;
            reinterpret_cast<float2*>(out)[i] = lg;

            if (loss_out) {
                // CE over 2-way softmax of [p, 1-p]
                const float ea  = expf(p);
                const float eb  = expf(1.0f - p);
                const float lse = logf(ea + eb);
                const int   li  = __ldg(l + i);
                const float chosen = (li == 0) ? p : (1.0f - p);
                my_loss = (lse - chosen) * invB;
            }
        }
    }

    if (loss_out) {
        if (lane == 0) sloss[wid] = my_loss;
        __syncthreads();
        if (threadIdx.x == 0) {
            float s = 0.0f;
            #pragma unroll
            for (int w = 0; w < WARPS_PER_BLOCK; w++) s += sloss[w];
            atomicAdd(loss_out, s);
        }
    }
}

extern "C" void kernel_launch(void* const* d_in, const int* in_sizes, int n_in,
                              void* d_out, int out_size)
{
    const int*    x  = (const int*)d_in[0];
    const int*    y  = (const int*)d_in[1];
    const int*    r  = (const int*)d_in[2];
    const int*    l  = (const int*)d_in[3];
    const float4* Wx = (const float4*)d_in[4];
    const float4* Wr = (const float4*)d_in[5];

    const int B = in_sizes[0];
    float* out = (float*)d_out;

    float* loss_ptr = (out_size > 2 * B) ? (out + 2 * B) : nullptr;
    if (loss_ptr) hin_zero_loss<<<1, 32>>>(loss_ptr);

    const int blocks = (B + WARPS_PER_BLOCK - 1) / WARPS_PER_BLOCK;
    hin_main<<<blocks, WARPS_PER_BLOCK * 32>>>(
        x, y, r, l, Wx, Wr, out, loss_ptr, B, 1.0f / (float)B);
}

// round 4
// speedup vs baseline: 1.1051x; 1.1051x over previous
#include <cuda_runtime.h>
#include <cstddef>

// Hin2vec layer: per-element gather-dot-sigmoid + CE loss.
// B=262144, N=1e6, R=64, H=128.
// R2: hoist s*(1-s) regularization into a precomputed 64x128 table
// (L1-resident), fast intrinsics, L2-only hint for the random Wx gathers.

#define H_DIM 128
#define R_DIM 64
#define WARPS_PER_BLOCK 8

__device__ float d_reWr[R_DIM * H_DIM];   // 32 KB: s*(1-s) of clamp(Wr)

// Prologue: build reWr table + zero the loss accumulator.
__global__ void hin_prep(const float* __restrict__ Wr, float* __restrict__ loss_ptr) {
    const int t = blockIdx.x * blockDim.x + threadIdx.x;
    if (t < R_DIM * H_DIM) {
        float e = fminf(fmaxf(Wr[t], -6.0f), 6.0f);
        float s = 1.0f / (1.0f + __expf(-e));
        d_reWr[t] = s * (1.0f - s);
    }
    if (t == 0 && loss_ptr) *loss_ptr = 0.0f;
}

__global__ void __launch_bounds__(WARPS_PER_BLOCK * 32)
hin_main(const int* __restrict__ x,
         const int* __restrict__ y,
         const int* __restrict__ r,
         const int* __restrict__ l,
         const float4* __restrict__ Wx,   // [N, H/4]
         float* __restrict__ out,         // [B, 2] logits
         float* __restrict__ loss_out,    // scalar (may be null)
         int B, float invB)
{
    const int wid  = threadIdx.x >> 5;
    const int lane = threadIdx.x & 31;
    const int i    = blockIdx.x * WARPS_PER_BLOCK + wid;

    __shared__ float sloss[WARPS_PER_BLOCK];

    float my_loss = 0.0f;

    if (i < B) {
        const int xi = __ldg(x + i);
        const int yi = __ldg(y + i);
        const int ri = __ldg(r + i);

        // Random 512B-row gathers: L2-only (no L1 reuse, keep L1 for reWr).
        const float4 ax = __ldcg(Wx + (unsigned)xi * (H_DIM / 4) + lane);
        const float4 ay = __ldcg(Wx + (unsigned)yi * (H_DIM / 4) + lane);
        // Hot 32KB table: L1-resident.
        const float4 rw = __ldg((const float4*)d_reWr + (unsigned)ri * (H_DIM / 4) + lane);

        float acc;
        acc  = ax.x * ay.x * rw.x;
        acc  = fmaf(ax.y * ay.y, rw.y, acc);
        acc  = fmaf(ax.z * ay.z, rw.z, acc);
        acc  = fmaf(ax.w * ay.w, rw.w, acc);

        // warp-wide dot reduce
        #pragma unroll
        for (int o = 16; o > 0; o >>= 1)
            acc += __shfl_xor_sync(0xFFFFFFFFu, acc, o);

        if (lane == 0) {
            const float p = 1.0f / (1.0f + __expf(-acc));
            float2 lg;
            lg.x = p;
            lg.y = 1.0f - p;
            reinterpret_cast<float2*>(out)[i] = lg;

            if (loss_out) {
                // CE over 2-way softmax of [p, 1-p]
                const float ea  = __expf(p);
                const float eb  = __expf(1.0f - p);
                const float lse = __logf(ea + eb);
                const int   li  = __ldg(l + i);
                const float chosen = (li == 0) ? p : (1.0f - p);
                my_loss = (lse - chosen) * invB;
            }
        }
    }

    if (loss_out) {
        if (lane == 0) sloss[wid] = my_loss;
        __syncthreads();
        if (threadIdx.x == 0) {
            float s = 0.0f;
            #pragma unroll
            for (int w = 0; w < WARPS_PER_BLOCK; w++) s += sloss[w];
            atomicAdd(loss_out, s);
        }
    }
}

extern "C" void kernel_launch(void* const* d_in, const int* in_sizes, int n_in,
                              void* d_out, int out_size)
{
    const int*    x  = (const int*)d_in[0];
    const int*    y  = (const int*)d_in[1];
    const int*    r  = (const int*)d_in[2];
    const int*    l  = (const int*)d_in[3];
    const float4* Wx = (const float4*)d_in[4];
    const float*  Wr = (const float*)d_in[5];

    const int B = in_sizes[0];
    float* out = (float*)d_out;
    float* loss_ptr = (out_size > 2 * B) ? (out + 2 * B) : nullptr;

    hin_prep<<<(R_DIM * H_DIM + 255) / 256, 256>>>(Wr, loss_ptr);

    const int blocks = (B + WARPS_PER_BLOCK - 1) / WARPS_PER_BLOCK;
    hin_main<<<blocks, WARPS_PER_BLOCK * 32>>>(
        x, y, r, l, Wx, out, loss_ptr, B, 1.0f / (float)B);
}

// round 6
// speedup vs baseline: 1.4169x; 1.2822x over previous
#include <cuda_runtime.h>
#include <cstddef>

// Hin2vec layer: B=262144, N=1e6, R=64, H=128.
// R5: 4 elements per warp -> 8 outstanding 512B gathers per warp (4x MLP),
// interleaved shuffle reduces, parallel per-lane epilogues.

#define H_DIM 128
#define R_DIM 64
#define WPB   8      // warps per block
#define ELEMS 4      // elements per warp

__device__ float d_reWr[R_DIM * H_DIM];   // 32 KB: s*(1-s) of clamp(Wr)

__global__ void hin_prep(const float* __restrict__ Wr, float* __restrict__ loss_ptr) {
    const int t = blockIdx.x * blockDim.x + threadIdx.x;
    if (t < R_DIM * H_DIM) {
        float e = fminf(fmaxf(Wr[t], -6.0f), 6.0f);
        float s = 1.0f / (1.0f + __expf(-e));
        d_reWr[t] = s * (1.0f - s);
    }
    if (t == 0 && loss_ptr) *loss_ptr = 0.0f;
}

__device__ __forceinline__ float dot_rw(float4 a, float4 b, float4 w) {
    float acc = a.x * b.x * w.x;
    acc = fmaf(a.y * b.y, w.y, acc);
    acc = fmaf(a.z * b.z, w.z, acc);
    acc = fmaf(a.w * b.w, w.w, acc);
    return acc;
}

__global__ void __launch_bounds__(WPB * 32)
hin_main(const int* __restrict__ x,
         const int* __restrict__ y,
         const int* __restrict__ r,
         const int* __restrict__ l,
         const float4* __restrict__ Wx,   // [N, H/4]
         float* __restrict__ out,         // [B, 2] logits
         float* __restrict__ loss_out,    // scalar (may be null)
         int B, float invB)
{
    const int wid  = threadIdx.x >> 5;
    const int lane = threadIdx.x & 31;
    const int base = (blockIdx.x * WPB + wid) * ELEMS;

    __shared__ float sloss[WPB];
    float my_loss = 0.0f;

    if (base < B) {
        // Broadcast index loads: all lanes same address -> 1 sector each.
        const int4 xv = *(const int4*)(x + base);
        const int4 yv = *(const int4*)(y + base);
        const int4 rv = *(const int4*)(r + base);

        // Issue all 8 random gathers before any dependent math (MLP=8).
        const float4 ax0 = __ldcg(Wx + (unsigned)xv.x * (H_DIM / 4) + lane);
        const float4 ay0 = __ldcg(Wx + (unsigned)yv.x * (H_DIM / 4) + lane);
        const float4 ax1 = __ldcg(Wx + (unsigned)xv.y * (H_DIM / 4) + lane);
        const float4 ay1 = __ldcg(Wx + (unsigned)yv.y * (H_DIM / 4) + lane);
        const float4 ax2 = __ldcg(Wx + (unsigned)xv.z * (H_DIM / 4) + lane);
        const float4 ay2 = __ldcg(Wx + (unsigned)yv.z * (H_DIM / 4) + lane);
        const float4 ax3 = __ldcg(Wx + (unsigned)xv.w * (H_DIM / 4) + lane);
        const float4 ay3 = __ldcg(Wx + (unsigned)yv.w * (H_DIM / 4) + lane);

        const float4* RW = (const float4*)d_reWr;   // hot 32KB, L1-resident
        const float4 rw0 = __ldg(RW + (unsigned)rv.x * (H_DIM / 4) + lane);
        const float4 rw1 = __ldg(RW + (unsigned)rv.y * (H_DIM / 4) + lane);
        const float4 rw2 = __ldg(RW + (unsigned)rv.z * (H_DIM / 4) + lane);
        const float4 rw3 = __ldg(RW + (unsigned)rv.w * (H_DIM / 4) + lane);

        float a0 = dot_rw(ax0, ay0, rw0);
        float a1 = dot_rw(ax1, ay1, rw1);
        float a2 = dot_rw(ax2, ay2, rw2);
        float a3 = dot_rw(ax3, ay3, rw3);

        // Four independent butterfly reductions, interleaved (latency overlaps).
        #pragma unroll
        for (int o = 16; o > 0; o >>= 1) {
            a0 += __shfl_xor_sync(0xFFFFFFFFu, a0, o);
            a1 += __shfl_xor_sync(0xFFFFFFFFu, a1, o);
            a2 += __shfl_xor_sync(0xFFFFFFFFu, a2, o);
            a3 += __shfl_xor_sync(0xFFFFFFFFu, a3, o);
        }

        // Lanes 0..3 each finish one element in parallel.
        if (lane < ELEMS) {
            const float acc = (lane == 0) ? a0 : (lane == 1) ? a1 : (lane == 2) ? a2 : a3;
            const float p = 1.0f / (1.0f + __expf(-acc));

            float2 lg;                       // coalesced 4x float2 store
            lg.x = p;
            lg.y = 1.0f - p;
            reinterpret_cast<float2*>(out)[base + lane] = lg;

            if (loss_out) {
                const float ea  = __expf(p);
                const float eb  = __expf(1.0f - p);
                const float lse = __logf(ea + eb);
                const int   li  = __ldg(l + base + lane);
                const float chosen = (li == 0) ? p : (1.0f - p);
                my_loss = (lse - chosen) * invB;
            }
        }
    }

    if (loss_out) {
        // Sum lanes 0..3 into lane 0 (other lanes carry 0).
        my_loss += __shfl_xor_sync(0xFFFFFFFFu, my_loss, 1);
        my_loss += __shfl_xor_sync(0xFFFFFFFFu, my_loss, 2);
        if (lane == 0) sloss[wid] = my_loss;
        __syncthreads();
        if (threadIdx.x == 0) {
            float s = 0.0f;
            #pragma unroll
            for (int w = 0; w < WPB; w++) s += sloss[w];
            atomicAdd(loss_out, s);
        }
    }
}

extern "C" void kernel_launch(void* const* d_in, const int* in_sizes, int n_in,
                              void* d_out, int out_size)
{
    const int*    x  = (const int*)d_in[0];
    const int*    y  = (const int*)d_in[1];
    const int*    r  = (const int*)d_in[2];
    const int*    l  = (const int*)d_in[3];
    const float4* Wx = (const float4*)d_in[4];
    const float*  Wr = (const float*)d_in[5];

    const int B = in_sizes[0];
    float* out = (float*)d_out;
    float* loss_ptr = (out_size > 2 * B) ? (out + 2 * B) : nullptr;

    hin_prep<<<(R_DIM * H_DIM + 255) / 256, 256>>>(Wr, loss_ptr);

    const int elems_per_block = WPB * ELEMS;
    const int blocks = (B + elems_per_block - 1) / elems_per_block;
    hin_main<<<blocks, WPB * 32>>>(
        x, y, r, l, Wx, out, loss_ptr, B, 1.0f / (float)B);
}